// round 13
// baseline (speedup 1.0000x reference)
#include <cuda_runtime.h>
#include <cuda_bf16.h>

// Lower-triangular packed index
#define TI(i,j) (((i)*((i)+1))/2 + (j))

#define BATCH 4
#define SEQ   64
#define NBT   (BATCH*SEQ)   // 256
#define NV    2000
#define LOG2PI_F 1.8378770664093453f

// ---------- device scratch (no allocations allowed) ----------
__device__ float  g_lam0[NBT * 36];
__device__ float  g_eta0[NBT * 8];
__device__ float  g_c0[NBT];
__device__ float4 g_vd0[NV], g_vd1[NV];   // per v: diag precision 1/cho^2
__device__ float4 g_ve0[NV], g_ve1[NV];   // per v: eta1 = mu/cho^2
__device__ float  g_vc1[NV];              // per v: 0.5*(logdet1 - q1)

// ---------- packed f32x2 helpers (FFMA2 path, sm_103a) ----------
typedef unsigned long long u64;
#define PK1F2  0x3F8000003F800000ULL   // {1.0f, 1.0f}
#define NEG1F2 0xBF800000BF800000ULL   // {-1.0f, -1.0f}

__device__ __forceinline__ u64 pk2(float a, float b) {
    u64 r; asm("mov.b64 %0, {%1,%2};" : "=l"(r) : "f"(a), "f"(b)); return r;
}
__device__ __forceinline__ void upk2(u64 x, float& a, float& b) {
    asm("mov.b64 {%0,%1}, %2;" : "=f"(a), "=f"(b) : "l"(x));
}
__device__ __forceinline__ u64 f2fma(u64 a, u64 b, u64 c) {
    u64 d; asm("fma.rn.f32x2 %0, %1, %2, %3;" : "=l"(d) : "l"(a), "l"(b), "l"(c)); return d;
}
__device__ __forceinline__ u64 f2mul(u64 a, u64 b) {
    u64 d; asm("mul.rn.f32x2 %0, %1, %2;" : "=l"(d) : "l"(a), "l"(b)); return d;
}
__device__ __forceinline__ u64 f2add(u64 a, u64 b) {
    u64 d; asm("add.rn.f32x2 %0, %1, %2;" : "=l"(d) : "l"(a), "l"(b)); return d;
}

// ---------- 8x8 in-register Cholesky (scalar, lower-tri packed) ----------
template<bool LD>
__device__ __forceinline__ void chol8(float* A, float* invd, float& lp1, float& lp2) {
#pragma unroll
    for (int k = 0; k < 8; k++) {
        float p = A[TI(k,k)];
        if (LD) { if (k < 4) lp1 *= p; else lp2 *= p; }
        float r = rsqrtf(p);
        invd[k] = r;
#pragma unroll
        for (int i = k + 1; i < 8; i++) A[TI(i,k)] *= r;
#pragma unroll
        for (int i = k + 1; i < 8; i++) {
#pragma unroll
            for (int j = k + 1; j <= i; j++)
                A[TI(i,j)] = fmaf(-A[TI(i,k)], A[TI(j,k)], A[TI(i,j)]);
        }
    }
}

// =====================================================================
// Fused prep kernel:
//   blocks 0..15 : per-vocab precompute (vprep)
//   block  16    : setup + word-prep + sequential scan + c0 tail
// Dynamic smem layout (floats):
//   stLam[9216] stEta[2048] swl[2048] swm[2048] sW[256] sLm[256] setv[16]
// =====================================================================
#define SM_FLOATS 15888

__global__ void __launch_bounds__(128) prep_kernel(
    const int*   __restrict__ sent,
    const float* __restrict__ emu,
    const float* __restrict__ echo,
    const float* __restrict__ tmu,
    const float* __restrict__ tcho,
    const float* __restrict__ dmu,
    const float* __restrict__ dcho)
{
    int tid = threadIdx.x;

    if (blockIdx.x < 16) {
        // ---------------- vprep ----------------
        int v = blockIdx.x * 128 + tid;
        if (v >= NV) return;
        float d[8], e[8];
        float q1 = 0.f, p1 = 1.f, p2 = 1.f;
#pragma unroll
        for (int i = 0; i < 8; i++) {
            float m = dmu[v * 8 + i];
            float c = dcho[v * 8 + i];
            float di = 1.0f / (c * c);
            d[i] = di;
            e[i] = m * di;
            q1 = fmaf(e[i], m, q1);
            if (i < 4) p1 *= di; else p2 *= di;
        }
        float ld1 = __logf(p1) + __logf(p2);
        g_vd0[v] = make_float4(d[0], d[1], d[2], d[3]);
        g_vd1[v] = make_float4(d[4], d[5], d[6], d[7]);
        g_ve0[v] = make_float4(e[0], e[1], e[2], e[3]);
        g_ve1[v] = make_float4(e[4], e[5], e[6], e[7]);
        g_vc1[v] = 0.5f * (ld1 - q1);
        return;
    }

    // ---------------- scan block ----------------
    extern __shared__ float sm[];
    float* stLam = sm;             // 9216 : staged lam0 per bt (36 each)
    float* stEta = sm + 9216;      // 2048 : staged eta0 per bt (8 each)
    float* swl   = sm + 11264;     // 2048 : word precision per bt
    float* swm   = sm + 13312;     // 2048 : word mu*precision per bt
    float* sW    = sm + 15360;     // 256
    float* sLm   = sm + 15616;     // 256  : lam_t (16x16)
    float* setv  = sm + 15872;     // 16   : eta_t

    // W = inv(Tc), Tc lower-triangular. Column j per thread.
    if (tid < 16) {
        int j = tid;
        for (int i = 0; i < 16; i++) {
            if (i < j) { sW[i * 16 + j] = 0.f; }
            else {
                float s = (i == j) ? 1.0f : 0.0f;
                for (int k = j; k < i; k++) s = fmaf(-tcho[i * 16 + k], sW[k * 16 + j], s);
                sW[i * 16 + j] = s / tcho[i * 16 + i];
            }
        }
    }
    __syncthreads();

    // lam_t = W W^T
    for (int e = tid; e < 256; e += 128) {
        int i = e >> 4, j = e & 15;
        int m = i < j ? i : j;
        float s = 0.f;
        for (int k = 0; k <= m; k++) s = fmaf(sW[i * 16 + k], sW[j * 16 + k], s);
        sLm[i * 16 + j] = s;
    }
    __syncthreads();

    // eta_t = lam_t @ mu
    if (tid < 16) {
        float s = 0.f;
        for (int k = 0; k < 16; k++) s = fmaf(sLm[tid * 16 + k], tmu[k], s);
        setv[tid] = s;
    }

    // word-level prep: lw = 1/cho^2, wml = mu*lw for all 256 (b,t)
    for (int q = tid; q < NBT; q += 128) {
        int tok = sent[q];
#pragma unroll
        for (int i = 0; i < 8; i++) {
            float c = echo[tok * 8 + i];
            float lw = 1.0f / (c * c);
            swl[q * 8 + i] = lw;
            swm[q * 8 + i] = emu[tok * 8 + i] * lw;
        }
    }
    __syncthreads();

    // ---- per-warp batch scan ----
    int w = tid >> 5, lane = tid & 31;
    int b = w;
    int lj = lane & 15;             // column id within replica group
    int cj = lj & 7;                // clamped column for loads

    // preload lam_t blocks into registers
    float Laa[36];
#pragma unroll
    for (int i = 0; i < 8; i++)
#pragma unroll
        for (int j = 0; j <= i; j++) Laa[TI(i,j)] = sLm[i * 16 + j];
    float Bcol[8], Ccol[8], eta_ta[8], etb[8];
#pragma unroll
    for (int i = 0; i < 8; i++) {
        Bcol[i]   = sLm[i * 16 + 8 + cj];
        Ccol[i]   = sLm[(8 + i) * 16 + 8 + cj];
        eta_ta[i] = setv[i];
        etb[i]    = setv[8 + i];
    }

    float lam1[36], eta1[8];
#pragma unroll
    for (int i = 0; i < 8; i++) {
        eta1[i] = 0.f;
#pragma unroll
        for (int j = 0; j <= i; j++) lam1[TI(i,j)] = (i == j) ? 1.0f : 0.0f;
    }

    for (int t = 0; t < 64; t++) {
        int bt = b * 64 + t;

        // word data (smem, no divisions in-loop)
        float lwv = swl[bt * 8 + cj];          // per-lane diag precision
        float wml[8];
#pragma unroll
        for (int i = 0; i < 8; i++) wml[i] = swm[bt * 8 + i];   // broadcast

        // A = lam_t_aa + lam1 ; Cholesky (replicated)
        float A[36];
#pragma unroll
        for (int i = 0; i < 8; i++)
#pragma unroll
            for (int j = 0; j <= i; j++)
                A[TI(i,j)] = Laa[TI(i,j)] + lam1[TI(i,j)];

        float invd[8], du1, du2;
        chol8<false>(A, invd, du1, du2);

        // 9-RHS forward solve (replicated in both 16-lane groups)
        float rhs[8];
        bool isB = (lj < 8);
#pragma unroll
        for (int i = 0; i < 8; i++)
            rhs[i] = isB ? Bcol[i] : (eta_ta[i] + eta1[i]);

        float y[8];
#pragma unroll
        for (int i = 0; i < 8; i++) {
            float s = rhs[i];
#pragma unroll
            for (int j = 0; j < i; j++) s = fmaf(-A[TI(i,j)], y[j], s);
            y[i] = s * invd[i];
        }

        // S = Y^T Y split across the two replica groups: group0 k=0..3, group1 k=4..7
        float ss[8] = {0,0,0,0,0,0,0,0};
        unsigned gbase = lane & 16;
#pragma unroll
        for (int kk = 0; kk < 4; kk++) {
            float yk = (lane & 16) ? y[kk + 4] : y[kk];
#pragma unroll
            for (int i = 0; i < 8; i++) {
                float yki = __shfl_sync(0xffffffffu, yk, gbase + i);
                ss[i] = fmaf(yki, yk, ss[i]);
            }
        }
#pragma unroll
        for (int i = 0; i < 8; i++)
            ss[i] += __shfl_xor_sync(0xffffffffu, ss[i], 16);

        // distributed new state: lane j holds column j of lam2; lane 8 holds eta2
        float nvd[8], etp[8];
#pragma unroll
        for (int i = 0; i < 8; i++) {
            float nv = Ccol[i] - ss[i];
            if (lj == i) nv += lwv;
            nvd[i] = nv;
            etp[i] = etb[i] + wml[i] - ss[i];   // valid on lane 8
        }

        // stage to smem (distributed stores)
#pragma unroll
        for (int i = 0; i < 8; i++) {
            if (lane < 16 && lj <= i) stLam[bt * 36 + TI(i, lj)] = nvd[i];
            if (lane == 8)            stEta[bt * 8 + i] = etp[i];
        }

        // replicate for next iteration
#pragma unroll
        for (int i = 0; i < 8; i++) {
#pragma unroll
            for (int j = 0; j <= i; j++)
                lam1[TI(i,j)] = __shfl_sync(0xffffffffu, nvd[i], j);
            eta1[i] = __shfl_sync(0xffffffffu, etp[i], 8);
        }
    }
    __syncthreads();

    // bulk coalesced copy to gmem
    {
        const float4* s4 = (const float4*)stLam;
        float4* d4 = (float4*)g_lam0;
        for (int q = tid; q < (NBT * 36) / 4; q += 128) d4[q] = s4[q];
        const float4* e4 = (const float4*)stEta;
        float4* de = (float4*)g_eta0;
        for (int q = tid; q < (NBT * 8) / 4; q += 128) de[q] = e4[q];
    }

    // c0 tail: 2 bt per thread, read staging from smem
    for (int bt = tid; bt < NBT; bt += 128) {
        float A[36];
#pragma unroll
        for (int q = 0; q < 36; q++) A[q] = stLam[bt * 36 + q];
        float invd[8], p1 = 1.f, p2 = 1.f;
        chol8<true>(A, invd, p1, p2);
        float z[8], q0 = 0.f;
#pragma unroll
        for (int i = 0; i < 8; i++) {
            float s = stEta[bt * 8 + i];
#pragma unroll
            for (int j = 0; j < i; j++) s = fmaf(-A[TI(i,j)], z[j], s);
            z[i] = s * invd[i];
            q0 = fmaf(z[i], z[i], q0);
        }
        float ld0 = __logf(p1) + __logf(p2);
        g_c0[bt] = 0.5f * (ld0 - q0) - 4.0f * LOG2PI_F;
    }
}

// =====================================================================
// Main phase: packed f32x2, 2 vocab items per thread
// grid (8, 256), block 128; thread tid<125 handles v0=bx*250+tid, v1=v0+125
// =====================================================================
__global__ void __launch_bounds__(128) main_kernel(float* __restrict__ out) {
    __shared__ u64  slp[36];
    __shared__ u64  sep[8];
    __shared__ float sc0s;

    int bt = blockIdx.y;
    int tid = threadIdx.x;
    if (tid < 36) { float s = g_lam0[bt * 36 + tid]; slp[tid] = pk2(s, s); }
    else if (tid < 44) { float s = g_eta0[bt * 8 + (tid - 36)]; sep[tid - 36] = pk2(s, s); }
    else if (tid == 44) sc0s = g_c0[bt];
    __syncthreads();

    if (tid >= 125) return;
    int v0 = blockIdx.x * 250 + tid;
    int v1 = v0 + 125;

    float4 a0 = g_vd0[v0], a1 = g_vd1[v0];
    float4 b0 = g_vd0[v1], b1 = g_vd1[v1];
    float4 ea0 = g_ve0[v0], ea1 = g_ve1[v0];
    float4 eb0 = g_ve0[v1], eb1 = g_ve1[v1];
    float c1a = g_vc1[v0], c1b = g_vc1[v1];

    u64 ddp[8] = { pk2(a0.x,b0.x), pk2(a0.y,b0.y), pk2(a0.z,b0.z), pk2(a0.w,b0.w),
                   pk2(a1.x,b1.x), pk2(a1.y,b1.y), pk2(a1.z,b1.z), pk2(a1.w,b1.w) };
    u64 eep[8] = { pk2(ea0.x,eb0.x), pk2(ea0.y,eb0.y), pk2(ea0.z,eb0.z), pk2(ea0.w,eb0.w),
                   pk2(ea1.x,eb1.x), pk2(ea1.y,eb1.y), pk2(ea1.z,eb1.z), pk2(ea1.w,eb1.w) };

    u64 A2[36];
#pragma unroll
    for (int i = 0; i < 8; i++)
#pragma unroll
        for (int j = 0; j <= i; j++)
            A2[TI(i,j)] = (i == j) ? f2add(slp[TI(i,j)], ddp[i]) : slp[TI(i,j)];

    const u64 NEG1 = NEG1F2;
    u64 nInv[8];
    u64 pp1 = PK1F2, pp2 = PK1F2;
#pragma unroll
    for (int k = 0; k < 8; k++) {
        u64 piv = A2[TI(k,k)];
        if (k < 4) pp1 = f2mul(pp1, piv); else pp2 = f2mul(pp2, piv);
        float pl, ph; upk2(piv, pl, ph);
        u64 r2 = pk2(rsqrtf(pl), rsqrtf(ph));
        nInv[k] = f2mul(r2, NEG1);
#pragma unroll
        for (int i = k + 1; i < 8; i++) A2[TI(i,k)] = f2mul(A2[TI(i,k)], r2);
#pragma unroll
        for (int i = k + 1; i < 8; i++) {
            u64 nl = f2mul(A2[TI(i,k)], NEG1);
#pragma unroll
            for (int j = k + 1; j <= i; j++)
                A2[TI(i,j)] = f2fma(nl, A2[TI(j,k)], A2[TI(i,j)]);
        }
    }

    // forward solve with negated z (zn = -z) so plain FFMA2 accumulates s - A*z
    u64 zn[8], p3 = 0ULL;
#pragma unroll
    for (int i = 0; i < 8; i++) {
        u64 s = f2add(sep[i], eep[i]);
#pragma unroll
        for (int j = 0; j < i; j++) s = f2fma(A2[TI(i,j)], zn[j], s);
        zn[i] = f2mul(s, nInv[i]);
        p3 = f2fma(zn[i], zn[i], p3);
    }

    float l1a, l1b, l2a, l2b, p3a, p3b;
    upk2(pp1, l1a, l1b);
    upk2(pp2, l2a, l2b);
    upk2(p3, p3a, p3b);
    float base = sc0s;
    float ra = base + c1a + 0.5f * (p3a - (__logf(l1a) + __logf(l2a)));
    float rb = base + c1b + 0.5f * (p3b - (__logf(l1b) + __logf(l2b)));
    out[bt * NV + v0] = ra;
    out[bt * NV + v1] = rb;
}

// ---------- launch ----------
extern "C" void kernel_launch(void* const* d_in, const int* in_sizes, int n_in,
                              void* d_out, int out_size) {
    const int*   sent = (const int*)  d_in[0];
    // d_in[1] = masks (all ones, unused by reference math)
    const float* emu  = (const float*)d_in[2];
    const float* echo = (const float*)d_in[3];
    const float* tmu  = (const float*)d_in[4];
    const float* tcho = (const float*)d_in[5];
    const float* dmu  = (const float*)d_in[6];
    const float* dcho = (const float*)d_in[7];
    float* out = (float*)d_out;

    static const size_t smem_bytes = SM_FLOATS * sizeof(float);
    cudaFuncSetAttribute(prep_kernel, cudaFuncAttributeMaxDynamicSharedMemorySize,
                         (int)smem_bytes);

    prep_kernel<<<17, 128, smem_bytes>>>(sent, emu, echo, tmu, tcho, dmu, dcho);
    main_kernel<<<dim3(8, NBT), 128>>>(out);
}

// round 14
// speedup vs baseline: 1.0473x; 1.0473x over previous
#include <cuda_runtime.h>
#include <cuda_bf16.h>

// Lower-triangular packed index
#define TI(i,j) (((i)*((i)+1))/2 + (j))

#define BATCH 4
#define SEQ   64
#define NBT   (BATCH*SEQ)   // 256
#define NV    2000
#define LOG2PI_F 1.8378770664093453f

// ---------- device scratch (no allocations allowed) ----------
__device__ float  g_lam0[NBT * 36];
__device__ float  g_eta0[NBT * 8];
__device__ float  g_c0[NBT];
__device__ float4 g_vd0[NV], g_vd1[NV];   // per v: diag precision 1/cho^2
__device__ float4 g_ve0[NV], g_ve1[NV];   // per v: eta1 = mu/cho^2
__device__ float  g_vc1[NV];              // per v: 0.5*(logdet1 - q1)

// ---------- packed f32x2 helpers (FFMA2 path, sm_103a) ----------
typedef unsigned long long u64;
#define PK1F2  0x3F8000003F800000ULL   // {1.0f, 1.0f}
#define NEG1F2 0xBF800000BF800000ULL   // {-1.0f, -1.0f}

__device__ __forceinline__ u64 pk2(float a, float b) {
    u64 r; asm("mov.b64 %0, {%1,%2};" : "=l"(r) : "f"(a), "f"(b)); return r;
}
__device__ __forceinline__ void upk2(u64 x, float& a, float& b) {
    asm("mov.b64 {%0,%1}, %2;" : "=f"(a), "=f"(b) : "l"(x));
}
__device__ __forceinline__ u64 f2fma(u64 a, u64 b, u64 c) {
    u64 d; asm("fma.rn.f32x2 %0, %1, %2, %3;" : "=l"(d) : "l"(a), "l"(b), "l"(c)); return d;
}
__device__ __forceinline__ u64 f2mul(u64 a, u64 b) {
    u64 d; asm("mul.rn.f32x2 %0, %1, %2;" : "=l"(d) : "l"(a), "l"(b)); return d;
}
__device__ __forceinline__ u64 f2add(u64 a, u64 b) {
    u64 d; asm("add.rn.f32x2 %0, %1, %2;" : "=l"(d) : "l"(a), "l"(b)); return d;
}

// ---------- 8x8 in-register Cholesky (scalar, lower-tri packed) ----------
template<bool LD>
__device__ __forceinline__ void chol8(float* A, float* invd, float& lp1, float& lp2) {
#pragma unroll
    for (int k = 0; k < 8; k++) {
        float p = A[TI(k,k)];
        if (LD) { if (k < 4) lp1 *= p; else lp2 *= p; }
        float r = rsqrtf(p);
        invd[k] = r;
#pragma unroll
        for (int i = k + 1; i < 8; i++) A[TI(i,k)] *= r;
#pragma unroll
        for (int i = k + 1; i < 8; i++) {
#pragma unroll
            for (int j = k + 1; j <= i; j++)
                A[TI(i,j)] = fmaf(-A[TI(i,k)], A[TI(j,k)], A[TI(i,j)]);
        }
    }
}

// =====================================================================
// Fused prep kernel:
//   blocks 0..15 : per-vocab precompute (vprep)
//   block  16    : setup + word-prep + sequential scan + c0 tail
// Dynamic smem layout (floats):
//   stLam[9216] stEta[2048] swl[2048] swm[2048] sW[256] sLm[256] setv[16]
// =====================================================================
#define SM_FLOATS 15888

__global__ void __launch_bounds__(128) prep_kernel(
    const int*   __restrict__ sent,
    const float* __restrict__ emu,
    const float* __restrict__ echo,
    const float* __restrict__ tmu,
    const float* __restrict__ tcho,
    const float* __restrict__ dmu,
    const float* __restrict__ dcho)
{
    int tid = threadIdx.x;

    if (blockIdx.x < 16) {
        // ---------------- vprep ----------------
        int v = blockIdx.x * 128 + tid;
        if (v >= NV) return;
        float d[8], e[8];
        float q1 = 0.f, p1 = 1.f, p2 = 1.f;
#pragma unroll
        for (int i = 0; i < 8; i++) {
            float m = dmu[v * 8 + i];
            float c = dcho[v * 8 + i];
            float di = 1.0f / (c * c);
            d[i] = di;
            e[i] = m * di;
            q1 = fmaf(e[i], m, q1);
            if (i < 4) p1 *= di; else p2 *= di;
        }
        float ld1 = __logf(p1) + __logf(p2);
        g_vd0[v] = make_float4(d[0], d[1], d[2], d[3]);
        g_vd1[v] = make_float4(d[4], d[5], d[6], d[7]);
        g_ve0[v] = make_float4(e[0], e[1], e[2], e[3]);
        g_ve1[v] = make_float4(e[4], e[5], e[6], e[7]);
        g_vc1[v] = 0.5f * (ld1 - q1);
        return;
    }

    // ---------------- scan block ----------------
    extern __shared__ float sm[];
    float* stLam = sm;             // 9216 : staged lam0 per bt (36 each)
    float* stEta = sm + 9216;      // 2048 : staged eta0 per bt (8 each)
    float* swl   = sm + 11264;     // 2048 : word precision per bt
    float* swm   = sm + 13312;     // 2048 : word mu*precision per bt
    float* sW    = sm + 15360;     // 256
    float* sLm   = sm + 15616;     // 256  : lam_t (16x16)
    float* setv  = sm + 15872;     // 16   : eta_t

    // W = inv(Tc), Tc lower-triangular. Column j per thread.
    if (tid < 16) {
        int j = tid;
        for (int i = 0; i < 16; i++) {
            if (i < j) { sW[i * 16 + j] = 0.f; }
            else {
                float s = (i == j) ? 1.0f : 0.0f;
                for (int k = j; k < i; k++) s = fmaf(-tcho[i * 16 + k], sW[k * 16 + j], s);
                sW[i * 16 + j] = s / tcho[i * 16 + i];
            }
        }
    }
    __syncthreads();

    // lam_t = W W^T
    for (int e = tid; e < 256; e += 128) {
        int i = e >> 4, j = e & 15;
        int m = i < j ? i : j;
        float s = 0.f;
        for (int k = 0; k <= m; k++) s = fmaf(sW[i * 16 + k], sW[j * 16 + k], s);
        sLm[i * 16 + j] = s;
    }
    __syncthreads();

    // eta_t = lam_t @ mu
    if (tid < 16) {
        float s = 0.f;
        for (int k = 0; k < 16; k++) s = fmaf(sLm[tid * 16 + k], tmu[k], s);
        setv[tid] = s;
    }

    // word-level prep: lw = 1/cho^2, wml = mu*lw for all 256 (b,t)
    for (int q = tid; q < NBT; q += 128) {
        int tok = sent[q];
#pragma unroll
        for (int i = 0; i < 8; i++) {
            float c = echo[tok * 8 + i];
            float lw = 1.0f / (c * c);
            swl[q * 8 + i] = lw;
            swm[q * 8 + i] = emu[tok * 8 + i] * lw;
        }
    }
    __syncthreads();

    // ---- per-warp batch scan ----
    int w = tid >> 5, lane = tid & 31;
    int b = w;
    int lj = lane & 15;             // column id within replica group
    int cj = lj & 7;                // clamped column for loads

    // preload lam_t blocks into registers
    float Laa[36];
#pragma unroll
    for (int i = 0; i < 8; i++)
#pragma unroll
        for (int j = 0; j <= i; j++) Laa[TI(i,j)] = sLm[i * 16 + j];
    float Bcol[8], Ccol[8], eta_ta[8], etb[8];
#pragma unroll
    for (int i = 0; i < 8; i++) {
        Bcol[i]   = sLm[i * 16 + 8 + cj];
        Ccol[i]   = sLm[(8 + i) * 16 + 8 + cj];
        eta_ta[i] = setv[i];
        etb[i]    = setv[8 + i];
    }

    float lam1[36], eta1[8];
#pragma unroll
    for (int i = 0; i < 8; i++) {
        eta1[i] = 0.f;
#pragma unroll
        for (int j = 0; j <= i; j++) lam1[TI(i,j)] = (i == j) ? 1.0f : 0.0f;
    }

    for (int t = 0; t < 64; t++) {
        int bt = b * 64 + t;

        // word data (smem, no divisions in-loop)
        float lwv = swl[bt * 8 + cj];          // per-lane diag precision
        float wml[8];
#pragma unroll
        for (int i = 0; i < 8; i++) wml[i] = swm[bt * 8 + i];   // broadcast

        // A = lam_t_aa + lam1 ; Cholesky (replicated)
        float A[36];
#pragma unroll
        for (int i = 0; i < 8; i++)
#pragma unroll
            for (int j = 0; j <= i; j++)
                A[TI(i,j)] = Laa[TI(i,j)] + lam1[TI(i,j)];

        float invd[8], du1, du2;
        chol8<false>(A, invd, du1, du2);

        // 9-RHS forward solve (replicated in both 16-lane groups)
        float rhs[8];
        bool isB = (lj < 8);
#pragma unroll
        for (int i = 0; i < 8; i++)
            rhs[i] = isB ? Bcol[i] : (eta_ta[i] + eta1[i]);

        float y[8];
#pragma unroll
        for (int i = 0; i < 8; i++) {
            float s = rhs[i];
#pragma unroll
            for (int j = 0; j < i; j++) s = fmaf(-A[TI(i,j)], y[j], s);
            y[i] = s * invd[i];
        }

        // S = Y^T Y split across the two replica groups: group0 k=0..3, group1 k=4..7
        float ss[8] = {0,0,0,0,0,0,0,0};
        unsigned gbase = lane & 16;
#pragma unroll
        for (int kk = 0; kk < 4; kk++) {
            float yk = (lane & 16) ? y[kk + 4] : y[kk];
#pragma unroll
            for (int i = 0; i < 8; i++) {
                float yki = __shfl_sync(0xffffffffu, yk, gbase + i);
                ss[i] = fmaf(yki, yk, ss[i]);
            }
        }
#pragma unroll
        for (int i = 0; i < 8; i++)
            ss[i] += __shfl_xor_sync(0xffffffffu, ss[i], 16);

        // distributed new state: lane j holds column j of lam2; lane 8 holds eta2
        float nvd[8], etp[8];
#pragma unroll
        for (int i = 0; i < 8; i++) {
            float nv = Ccol[i] - ss[i];
            if (lj == i) nv += lwv;
            nvd[i] = nv;
            etp[i] = etb[i] + wml[i] - ss[i];   // valid on lane 8
        }

        // stage to smem (distributed stores)
#pragma unroll
        for (int i = 0; i < 8; i++) {
            if (lane < 16 && lj <= i) stLam[bt * 36 + TI(i, lj)] = nvd[i];
            if (lane == 8)            stEta[bt * 8 + i] = etp[i];
        }

        // replicate for next iteration
#pragma unroll
        for (int i = 0; i < 8; i++) {
#pragma unroll
            for (int j = 0; j <= i; j++)
                lam1[TI(i,j)] = __shfl_sync(0xffffffffu, nvd[i], j);
            eta1[i] = __shfl_sync(0xffffffffu, etp[i], 8);
        }
    }
    __syncthreads();

    // bulk coalesced copy to gmem
    {
        const float4* s4 = (const float4*)stLam;
        float4* d4 = (float4*)g_lam0;
        for (int q = tid; q < (NBT * 36) / 4; q += 128) d4[q] = s4[q];
        const float4* e4 = (const float4*)stEta;
        float4* de = (float4*)g_eta0;
        for (int q = tid; q < (NBT * 8) / 4; q += 128) de[q] = e4[q];
    }

    // c0 tail: 2 bt per thread, read staging from smem
    for (int bt = tid; bt < NBT; bt += 128) {
        float A[36];
#pragma unroll
        for (int q = 0; q < 36; q++) A[q] = stLam[bt * 36 + q];
        float invd[8], p1 = 1.f, p2 = 1.f;
        chol8<true>(A, invd, p1, p2);
        float z[8], q0 = 0.f;
#pragma unroll
        for (int i = 0; i < 8; i++) {
            float s = stEta[bt * 8 + i];
#pragma unroll
            for (int j = 0; j < i; j++) s = fmaf(-A[TI(i,j)], z[j], s);
            z[i] = s * invd[i];
            q0 = fmaf(z[i], z[i], q0);
        }
        float ld0 = __logf(p1) + __logf(p2);
        g_c0[bt] = 0.5f * (ld0 - q0) - 4.0f * LOG2PI_F;
    }
}

// =====================================================================
// Main phase: packed f32x2, 2 vocab items per thread
// grid (8, 256), block 128; thread tid<125 handles v0=bx*250+tid, v1=v0+125
// =====================================================================
__global__ void __launch_bounds__(128) main_kernel(float* __restrict__ out) {
    __shared__ u64  slp[36];
    __shared__ u64  sep[8];
    __shared__ float sc0s;

    int bt = blockIdx.y;
    int tid = threadIdx.x;
    if (tid < 36) { float s = g_lam0[bt * 36 + tid]; slp[tid] = pk2(s, s); }
    else if (tid < 44) { float s = g_eta0[bt * 8 + (tid - 36)]; sep[tid - 36] = pk2(s, s); }
    else if (tid == 44) sc0s = g_c0[bt];
    __syncthreads();

    if (tid >= 125) return;
    int v0 = blockIdx.x * 250 + tid;
    int v1 = v0 + 125;

    float4 a0 = g_vd0[v0], a1 = g_vd1[v0];
    float4 b0 = g_vd0[v1], b1 = g_vd1[v1];
    float4 ea0 = g_ve0[v0], ea1 = g_ve1[v0];
    float4 eb0 = g_ve0[v1], eb1 = g_ve1[v1];
    float c1a = g_vc1[v0], c1b = g_vc1[v1];

    u64 ddp[8] = { pk2(a0.x,b0.x), pk2(a0.y,b0.y), pk2(a0.z,b0.z), pk2(a0.w,b0.w),
                   pk2(a1.x,b1.x), pk2(a1.y,b1.y), pk2(a1.z,b1.z), pk2(a1.w,b1.w) };
    u64 eep[8] = { pk2(ea0.x,eb0.x), pk2(ea0.y,eb0.y), pk2(ea0.z,eb0.z), pk2(ea0.w,eb0.w),
                   pk2(ea1.x,eb1.x), pk2(ea1.y,eb1.y), pk2(ea1.z,eb1.z), pk2(ea1.w,eb1.w) };

    u64 A2[36];
#pragma unroll
    for (int i = 0; i < 8; i++)
#pragma unroll
        for (int j = 0; j <= i; j++)
            A2[TI(i,j)] = (i == j) ? f2add(slp[TI(i,j)], ddp[i]) : slp[TI(i,j)];

    const u64 NEG1 = NEG1F2;
    u64 nInv[8];
    u64 pp1 = PK1F2, pp2 = PK1F2;
#pragma unroll
    for (int k = 0; k < 8; k++) {
        u64 piv = A2[TI(k,k)];
        if (k < 4) pp1 = f2mul(pp1, piv); else pp2 = f2mul(pp2, piv);
        float pl, ph; upk2(piv, pl, ph);
        u64 r2 = pk2(rsqrtf(pl), rsqrtf(ph));
        nInv[k] = f2mul(r2, NEG1);
#pragma unroll
        for (int i = k + 1; i < 8; i++) A2[TI(i,k)] = f2mul(A2[TI(i,k)], r2);
#pragma unroll
        for (int i = k + 1; i < 8; i++) {
            u64 nl = f2mul(A2[TI(i,k)], NEG1);
#pragma unroll
            for (int j = k + 1; j <= i; j++)
                A2[TI(i,j)] = f2fma(nl, A2[TI(j,k)], A2[TI(i,j)]);
        }
    }

    // forward solve with negated z (zn = -z) so plain FFMA2 accumulates s - A*z
    u64 zn[8], p3 = 0ULL;
#pragma unroll
    for (int i = 0; i < 8; i++) {
        u64 s = f2add(sep[i], eep[i]);
#pragma unroll
        for (int j = 0; j < i; j++) s = f2fma(A2[TI(i,j)], zn[j], s);
        zn[i] = f2mul(s, nInv[i]);
        p3 = f2fma(zn[i], zn[i], p3);
    }

    float l1a, l1b, l2a, l2b, p3a, p3b;
    upk2(pp1, l1a, l1b);
    upk2(pp2, l2a, l2b);
    upk2(p3, p3a, p3b);
    float base = sc0s;
    float ra = base + c1a + 0.5f * (p3a - (__logf(l1a) + __logf(l2a)));
    float rb = base + c1b + 0.5f * (p3b - (__logf(l1b) + __logf(l2b)));
    out[bt * NV + v0] = ra;
    out[bt * NV + v1] = rb;
}

// ---------- launch ----------
extern "C" void kernel_launch(void* const* d_in, const int* in_sizes, int n_in,
                              void* d_out, int out_size) {
    const int*   sent = (const int*)  d_in[0];
    // d_in[1] = masks (all ones, unused by reference math)
    const float* emu  = (const float*)d_in[2];
    const float* echo = (const float*)d_in[3];
    const float* tmu  = (const float*)d_in[4];
    const float* tcho = (const float*)d_in[5];
    const float* dmu  = (const float*)d_in[6];
    const float* dcho = (const float*)d_in[7];
    float* out = (float*)d_out;

    static const size_t smem_bytes = SM_FLOATS * sizeof(float);
    cudaFuncSetAttribute(prep_kernel, cudaFuncAttributeMaxDynamicSharedMemorySize,
                         (int)smem_bytes);

    prep_kernel<<<17, 128, smem_bytes>>>(sent, emu, echo, tmu, tcho, dmu, dcho);
    main_kernel<<<dim3(8, NBT), 128>>>(out);
}